// round 14
// baseline (speedup 1.0000x reference)
#include <cuda_runtime.h>
#include <cuda_bf16.h>
#include <cstdint>

#define N_NODES 50000
#define E_EDGES 800000
#define DIM 256
#define KTOT 512
#define YBLOCKS 391            // ceil(50000/128)
#define NCHUNK 4

// ---------------------------------------------------------------------------
// Scratch (static device globals — no allocation allowed)
// ---------------------------------------------------------------------------
__device__ float g_h1[N_NODES * DIM];
__device__ float g_h2[N_NODES * DIM];
__device__ __nv_bfloat16 g_aggH[N_NODES * DIM];
__device__ __nv_bfloat16 g_aggL[N_NODES * DIM];
__device__ __nv_bfloat16 g_pH0[N_NODES * DIM];
__device__ __nv_bfloat16 g_pL0[N_NODES * DIM];
__device__ __nv_bfloat16 g_pH1[N_NODES * DIM];
__device__ __nv_bfloat16 g_pL1[N_NODES * DIM];
__device__ int   g_cnt[N_NODES];
__device__ int   g_rowptr[N_NODES + 1];
__device__ int   g_cursor[N_NODES];
__device__ int   g_srcs[E_EDGES];
// Weight planes: [layer][k=512][n=256] bf16 hi/lo (k: rel 0..255, root 256..511)
__device__ __nv_bfloat16 g_Bh[3 * KTOT * DIM];
__device__ __nv_bfloat16 g_Bl[3 * KTOT * DIM];

// ---------------------------------------------------------------------------
// PTX helpers
// ---------------------------------------------------------------------------
__device__ __forceinline__ uint32_t smem_u32(const void* p) {
    uint32_t a;
    asm("{ .reg .u64 t; cvta.to.shared.u64 t, %1; cvt.u32.u64 %0, t; }"
        : "=r"(a) : "l"(p));
    return a;
}
__device__ __forceinline__ void ldm_x4(uint32_t* r, uint32_t addr) {
    asm volatile("ldmatrix.sync.aligned.m8n8.x4.shared.b16 {%0,%1,%2,%3}, [%4];"
                 : "=r"(r[0]), "=r"(r[1]), "=r"(r[2]), "=r"(r[3]) : "r"(addr));
}
__device__ __forceinline__ void ldm_x4_t(uint32_t* r, uint32_t addr) {
    asm volatile("ldmatrix.sync.aligned.m8n8.x4.trans.shared.b16 {%0,%1,%2,%3}, [%4];"
                 : "=r"(r[0]), "=r"(r[1]), "=r"(r[2]), "=r"(r[3]) : "r"(addr));
}
__device__ __forceinline__ void mma_bf16(float* c, const uint32_t* a, const uint32_t* b) {
    asm volatile("mma.sync.aligned.m16n8k16.row.col.f32.bf16.bf16.f32 "
                 "{%0,%1,%2,%3}, {%4,%5,%6,%7}, {%8,%9}, {%0,%1,%2,%3};"
                 : "+f"(c[0]), "+f"(c[1]), "+f"(c[2]), "+f"(c[3])
                 : "r"(a[0]), "r"(a[1]), "r"(a[2]), "r"(a[3]),
                   "r"(b[0]), "r"(b[1]));
}
__device__ __forceinline__ void cp16(uint32_t dst, const void* src, int szarg) {
    asm volatile("cp.async.cg.shared.global [%0], [%1], 16, %2;"
                 :: "r"(dst), "l"(src), "r"(szarg) : "memory");
}
__device__ __forceinline__ uint32_t pack_bf16(__nv_bfloat16 lo, __nv_bfloat16 hi) {
    return ((uint32_t)*(unsigned short*)&hi << 16) | *(unsigned short*)&lo;
}

// ---------------------------------------------------------------------------
// CSR build
// ---------------------------------------------------------------------------
__global__ void zero_cnt_kernel(int* __restrict__ cnt) {
    int i = blockIdx.x * blockDim.x + threadIdx.x;
    if (i < N_NODES) cnt[i] = 0;
}
__global__ void hist_kernel(const int* __restrict__ ei, int* __restrict__ cnt) {
    int e = blockIdx.x * blockDim.x + threadIdx.x;
    if (e < E_EDGES) {
        int d = ei[E_EDGES + e];
        if ((unsigned)d < N_NODES) atomicAdd(&cnt[d], 1);
    }
}
__global__ void scan_kernel(const int* __restrict__ cnt,
                            int* __restrict__ rowptr, int* __restrict__ cursor) {
    const int C = 49;
    int tid = threadIdx.x;
    int base = tid * C;
    int s = 0;
    for (int i = 0; i < C; i++) { int idx = base + i; if (idx < N_NODES) s += cnt[idx]; }
    int lane = tid & 31, warp = tid >> 5;
    int v = s;
#pragma unroll
    for (int o = 1; o < 32; o <<= 1) {
        int n = __shfl_up_sync(0xFFFFFFFFu, v, o);
        if (lane >= o) v += n;
    }
    __shared__ int wsum[32];
    if (lane == 31) wsum[warp] = v;
    __syncthreads();
    if (warp == 0) {
        int w = wsum[lane];
#pragma unroll
        for (int o = 1; o < 32; o <<= 1) {
            int n = __shfl_up_sync(0xFFFFFFFFu, w, o);
            if (lane >= o) w += n;
        }
        wsum[lane] = w;
    }
    __syncthreads();
    int excl = v - s + (warp > 0 ? wsum[warp - 1] : 0);
    int run = excl;
    for (int i = 0; i < C; i++) {
        int idx = base + i;
        if (idx < N_NODES) { rowptr[idx] = run; cursor[idx] = run; run += cnt[idx]; }
    }
    if (tid == blockDim.x - 1) rowptr[N_NODES] = run;
}
__global__ void fill_kernel(const int* __restrict__ ei,
                            int* __restrict__ cursor, int* __restrict__ srcs) {
    int e = blockIdx.x * blockDim.x + threadIdx.x;
    if (e < E_EDGES) {
        int d = ei[E_EDGES + e];
        int s = ei[e];
        if ((unsigned)d < N_NODES && (unsigned)s < N_NODES) {
            int p = atomicAdd(&cursor[d], 1);
            srcs[p] = s;
        }
    }
}

// ---------------------------------------------------------------------------
// Weight prep: W[k,n] -> [k][n] bf16 hi/lo planes (virtual K: Wrel then Wroot)
// ---------------------------------------------------------------------------
__global__ void prep_weights(const float* __restrict__ W1r, const float* __restrict__ W1o,
                             const float* __restrict__ W2r, const float* __restrict__ W2o,
                             const float* __restrict__ W3r, const float* __restrict__ W3o,
                             __nv_bfloat16* __restrict__ Bh, __nv_bfloat16* __restrict__ Bl) {
    int i = blockIdx.x * blockDim.x + threadIdx.x;
    if (i >= 3 * KTOT * DIM) return;
    int layer = i / (KTOT * DIM);
    int rem = i % (KTOT * DIM);
    int k = rem >> 8;
    int n = rem & 255;
    const float* Wr = (layer == 0) ? W1r : (layer == 1) ? W2r : W3r;
    const float* Wo = (layer == 0) ? W1o : (layer == 1) ? W2o : W3o;
    float w = (k < 256) ? Wr[k * 256 + n] : Wo[(k - 256) * 256 + n];
    __nv_bfloat16 hi = __float2bfloat16(w);
    __nv_bfloat16 lo = __float2bfloat16(w - __bfloat162float(hi));
    Bh[i] = hi;
    Bl[i] = lo;
}

// ---------------------------------------------------------------------------
// Split fp32 features into bf16 hi/lo planes (for x once per call)
// ---------------------------------------------------------------------------
__global__ void prep_x(const float4* __restrict__ x4,
                       __nv_bfloat16* __restrict__ pH, __nv_bfloat16* __restrict__ pL) {
    int i = blockIdx.x * blockDim.x + threadIdx.x;
    if (i >= N_NODES * DIM / 4) return;
    float4 v = x4[i];
    __nv_bfloat16 h0 = __float2bfloat16(v.x), h1 = __float2bfloat16(v.y);
    __nv_bfloat16 h2 = __float2bfloat16(v.z), h3 = __float2bfloat16(v.w);
    __nv_bfloat16 l0 = __float2bfloat16(v.x - __bfloat162float(h0));
    __nv_bfloat16 l1 = __float2bfloat16(v.y - __bfloat162float(h1));
    __nv_bfloat16 l2 = __float2bfloat16(v.z - __bfloat162float(h2));
    __nv_bfloat16 l3 = __float2bfloat16(v.w - __bfloat162float(h3));
    uint2 hp = make_uint2(pack_bf16(h0, h1), pack_bf16(h2, h3));
    uint2 lp = make_uint2(pack_bf16(l0, l1), pack_bf16(l2, l3));
    *(uint2*)&pH[i * 4] = hp;
    *(uint2*)&pL[i * 4] = lp;
}

// ---------------------------------------------------------------------------
// CSR gather aggregation over a node chunk -> bf16 hi/lo planes
// ---------------------------------------------------------------------------
__global__ void gather_agg_kernel(const float4* __restrict__ x4,
                                  const int* __restrict__ rowptr,
                                  const int* __restrict__ srcs,
                                  __nv_bfloat16* __restrict__ aggH,
                                  __nv_bfloat16* __restrict__ aggL,
                                  int nodeBase, int nodeEnd) {
    int node = nodeBase + blockIdx.x * 4 + (threadIdx.x >> 6);
    int t = threadIdx.x & 63;
    if (node >= nodeEnd) return;
    int beg = rowptr[node];
    int end = rowptr[node + 1];
    float4 a0 = make_float4(0.f, 0.f, 0.f, 0.f);
    float4 a1 = make_float4(0.f, 0.f, 0.f, 0.f);
    int e = beg;
    for (; e + 4 <= end; e += 4) {
        int s0 = srcs[e + 0], s1 = srcs[e + 1], s2 = srcs[e + 2], s3 = srcs[e + 3];
        float4 v0 = x4[(size_t)s0 * 64 + t];
        float4 v1 = x4[(size_t)s1 * 64 + t];
        float4 v2 = x4[(size_t)s2 * 64 + t];
        float4 v3 = x4[(size_t)s3 * 64 + t];
        a0.x += v0.x; a0.y += v0.y; a0.z += v0.z; a0.w += v0.w;
        a1.x += v1.x; a1.y += v1.y; a1.z += v1.z; a1.w += v1.w;
        a0.x += v2.x; a0.y += v2.y; a0.z += v2.z; a0.w += v2.w;
        a1.x += v3.x; a1.y += v3.y; a1.z += v3.z; a1.w += v3.w;
    }
    for (; e < end; e++) {
        int s0 = srcs[e];
        float4 v0 = x4[(size_t)s0 * 64 + t];
        a0.x += v0.x; a0.y += v0.y; a0.z += v0.z; a0.w += v0.w;
    }
    float4 r;
    r.x = a0.x + a1.x; r.y = a0.y + a1.y; r.z = a0.z + a1.z; r.w = a0.w + a1.w;
    __nv_bfloat16 h0 = __float2bfloat16(r.x), h1 = __float2bfloat16(r.y);
    __nv_bfloat16 h2 = __float2bfloat16(r.z), h3 = __float2bfloat16(r.w);
    __nv_bfloat16 l0 = __float2bfloat16(r.x - __bfloat162float(h0));
    __nv_bfloat16 l1 = __float2bfloat16(r.y - __bfloat162float(h1));
    __nv_bfloat16 l2 = __float2bfloat16(r.z - __bfloat162float(h2));
    __nv_bfloat16 l3 = __float2bfloat16(r.w - __bfloat162float(h3));
    size_t o = (size_t)node * 256 + t * 4;
    *(uint2*)&aggH[o] = make_uint2(pack_bf16(h0, h1), pack_bf16(h2, h3));
    *(uint2*)&aggL[o] = make_uint2(pack_bf16(l0, l1), pack_bf16(l2, l3));
}

// ---------------------------------------------------------------------------
// Tensor-core GEMM (mma.sync bf16, 3-pass Markidis split) + bias + ELU.
// Row-chunked: rowBase = (yBase + blockIdx.y) * 128.
// ---------------------------------------------------------------------------
#define AS_STRIDE 40
#define BS_STRIDE 136
#define A_PLANE_ELEMS (128 * AS_STRIDE)
#define B_PLANE_ELEMS (32 * BS_STRIDE)
#define SM_AH(buf) ((buf) * (A_PLANE_ELEMS * 2))
#define SM_AL(buf) (2 * A_PLANE_ELEMS * 2 + (buf) * (A_PLANE_ELEMS * 2))
#define SM_BH(buf) (4 * A_PLANE_ELEMS * 2 + (buf) * (B_PLANE_ELEMS * 2))
#define SM_BL(buf) (4 * A_PLANE_ELEMS * 2 + 2 * B_PLANE_ELEMS * 2 + (buf) * (B_PLANE_ELEMS * 2))
#define GEMM_SMEM (4 * A_PLANE_ELEMS * 2 + 4 * B_PLANE_ELEMS * 2)

__device__ __forceinline__ void load_tile(
    int it, uint32_t sAh, uint32_t sAl, uint32_t sBh, uint32_t sBl,
    int tid, int rowBase, int colBase,
    const __nv_bfloat16* aggH, const __nv_bfloat16* aggL,
    const __nv_bfloat16* inH, const __nv_bfloat16* inL,
    const __nv_bfloat16* BhG, const __nv_bfloat16* BlG) {
    int kglob = it * 32;
    const __nv_bfloat16* AH = (it < 8) ? aggH : inH;
    const __nv_bfloat16* AL = (it < 8) ? aggL : inL;
    int kc = kglob & 255;
#pragma unroll
    for (int p = 0; p < 2; p++) {
        int idx = tid + p * 256;
        int r = idx >> 2, c = idx & 3;
        int row = rowBase + r;
        int ok = (row < N_NODES);
        size_t off = (size_t)(ok ? row : 0) * 256 + kc + c * 8;
        int sz = ok ? 16 : 0;
        cp16(sAh + r * 80 + c * 16, AH + off, sz);
        cp16(sAl + r * 80 + c * 16, AL + off, sz);
    }
#pragma unroll
    for (int p = 0; p < 2; p++) {
        int idx = tid + p * 256;
        int r = idx >> 4, c = idx & 15;
        size_t off = (size_t)(kglob + r) * 256 + colBase + c * 8;
        cp16(sBh + r * 272 + c * 16, BhG + off, 16);
        cp16(sBl + r * 272 + c * 16, BlG + off, 16);
    }
    asm volatile("cp.async.commit_group;" ::: "memory");
}

__global__ void __launch_bounds__(256, 1)
gemm_mma(const __nv_bfloat16* __restrict__ aggH, const __nv_bfloat16* __restrict__ aggL,
         const __nv_bfloat16* __restrict__ inH, const __nv_bfloat16* __restrict__ inL,
         const __nv_bfloat16* __restrict__ BhG, const __nv_bfloat16* __restrict__ BlG,
         const float* __restrict__ bias, float* __restrict__ outF,
         __nv_bfloat16* __restrict__ outH, __nv_bfloat16* __restrict__ outL,
         int writePlanes, int yBase) {
    extern __shared__ char smem[];
    uint32_t sb = smem_u32(smem);
    int tid = threadIdx.x;
    int wid = tid >> 5;
    int lane = tid & 31;
    int rowBase = (yBase + blockIdx.y) * 128;
    int colBase = blockIdx.x * 128;
    int wm = wid >> 1;
    int wn = wid & 1;

    float acc[2][8][4];
#pragma unroll
    for (int i = 0; i < 2; i++)
#pragma unroll
        for (int j = 0; j < 8; j++)
#pragma unroll
            for (int q = 0; q < 4; q++) acc[i][j][q] = 0.f;

    load_tile(0, sb + SM_AH(0), sb + SM_AL(0), sb + SM_BH(0), sb + SM_BL(0),
              tid, rowBase, colBase, aggH, aggL, inH, inL, BhG, BlG);

    for (int it = 0; it < 16; it++) {
        int buf = it & 1;
        if (it < 15) {
            int nb = buf ^ 1;
            load_tile(it + 1, sb + SM_AH(nb), sb + SM_AL(nb), sb + SM_BH(nb), sb + SM_BL(nb),
                      tid, rowBase, colBase, aggH, aggL, inH, inL, BhG, BlG);
            asm volatile("cp.async.wait_group 1;" ::: "memory");
        } else {
            asm volatile("cp.async.wait_group 0;" ::: "memory");
        }
        __syncthreads();

        uint32_t Ah = sb + SM_AH(buf), Al = sb + SM_AL(buf);
        uint32_t Bh = sb + SM_BH(buf), Bl = sb + SM_BL(buf);
#pragma unroll
        for (int ks = 0; ks < 2; ks++) {
            int k0 = ks * 16;
            uint32_t ah[2][4], al[2][4];
            int arow = wm * 32 + (lane & 15);
            int akk = k0 + (lane >> 4) * 8;
#pragma unroll
            for (int mb = 0; mb < 2; mb++) {
                ldm_x4(ah[mb], Ah + ((arow + mb * 16) * AS_STRIDE + akk) * 2);
                ldm_x4(al[mb], Al + ((arow + mb * 16) * AS_STRIDE + akk) * 2);
            }
            uint32_t bh[8][2], bl[8][2];
            int brow = k0 + (lane & 15);
#pragma unroll
            for (int np = 0; np < 4; np++) {
                int ncol = wn * 64 + np * 16 + (lane >> 4) * 8;
                uint32_t rh[4], rl[4];
                ldm_x4_t(rh, Bh + (brow * BS_STRIDE + ncol) * 2);
                ldm_x4_t(rl, Bl + (brow * BS_STRIDE + ncol) * 2);
                bh[np * 2][0] = rh[0]; bh[np * 2][1] = rh[1];
                bh[np * 2 + 1][0] = rh[2]; bh[np * 2 + 1][1] = rh[3];
                bl[np * 2][0] = rl[0]; bl[np * 2][1] = rl[1];
                bl[np * 2 + 1][0] = rl[2]; bl[np * 2 + 1][1] = rl[3];
            }
#pragma unroll
            for (int mb = 0; mb < 2; mb++)
#pragma unroll
                for (int nb = 0; nb < 8; nb++) {
                    mma_bf16(acc[mb][nb], ah[mb], bh[nb]);
                    mma_bf16(acc[mb][nb], ah[mb], bl[nb]);
                    mma_bf16(acc[mb][nb], al[mb], bh[nb]);
                }
        }
        __syncthreads();
    }

#pragma unroll
    for (int mb = 0; mb < 2; mb++) {
        int row0 = rowBase + wm * 32 + mb * 16 + (lane >> 2);
#pragma unroll
        for (int nb = 0; nb < 8; nb++) {
            int col = colBase + wn * 64 + nb * 8 + (lane & 3) * 2;
            float b0 = bias[col], b1 = bias[col + 1];
#pragma unroll
            for (int half = 0; half < 2; half++) {
                int row = row0 + half * 8;
                if (row >= N_NODES) continue;
                float v0 = acc[mb][nb][half * 2 + 0] + b0;
                float v1 = acc[mb][nb][half * 2 + 1] + b1;
                v0 = (v0 > 0.f) ? v0 : expm1f(v0);
                v1 = (v1 > 0.f) ? v1 : expm1f(v1);
                size_t o = (size_t)row * 256 + col;
                *(float2*)(outF + o) = make_float2(v0, v1);
                if (writePlanes) {
                    __nv_bfloat16 h0 = __float2bfloat16(v0);
                    __nv_bfloat16 h1 = __float2bfloat16(v1);
                    __nv_bfloat16 l0 = __float2bfloat16(v0 - __bfloat162float(h0));
                    __nv_bfloat16 l1 = __float2bfloat16(v1 - __bfloat162float(h1));
                    *(uint32_t*)&outH[o] = pack_bf16(h0, h1);
                    *(uint32_t*)&outL[o] = pack_bf16(l0, l1);
                }
            }
        }
    }
}

// ---------------------------------------------------------------------------
// Launch: chunked gather->GEMM pipeline across two streams.
//   s2: CSR build | gather chunks (L0..L2)
//   s0: prep      | GEMM chunks, each gated on its gather event
// ---------------------------------------------------------------------------
extern "C" void kernel_launch(void* const* d_in, const int* in_sizes, int n_in,
                              void* d_out, int out_size) {
    const float* x       = (const float*)d_in[0];
    const int*   ei      = (const int*)d_in[1];
    const float* W1_rel  = (const float*)d_in[2];
    const float* b1      = (const float*)d_in[3];
    const float* W1_root = (const float*)d_in[4];
    const float* W2_rel  = (const float*)d_in[5];
    const float* b2      = (const float*)d_in[6];
    const float* W2_root = (const float*)d_in[7];
    const float* W3_rel  = (const float*)d_in[8];
    const float* b3      = (const float*)d_in[9];
    const float* W3_root = (const float*)d_in[10];
    float* out = (float*)d_out;

    float *h1, *h2;
    int *cnt, *rowptr, *cursor, *srcs;
    __nv_bfloat16 *Bh, *Bl, *aggH, *aggL, *pH0, *pL0, *pH1, *pL1;
    cudaGetSymbolAddress((void**)&h1, g_h1);
    cudaGetSymbolAddress((void**)&h2, g_h2);
    cudaGetSymbolAddress((void**)&cnt, g_cnt);
    cudaGetSymbolAddress((void**)&rowptr, g_rowptr);
    cudaGetSymbolAddress((void**)&cursor, g_cursor);
    cudaGetSymbolAddress((void**)&srcs, g_srcs);
    cudaGetSymbolAddress((void**)&Bh, g_Bh);
    cudaGetSymbolAddress((void**)&Bl, g_Bl);
    cudaGetSymbolAddress((void**)&aggH, g_aggH);
    cudaGetSymbolAddress((void**)&aggL, g_aggL);
    cudaGetSymbolAddress((void**)&pH0, g_pH0);
    cudaGetSymbolAddress((void**)&pL0, g_pL0);
    cudaGetSymbolAddress((void**)&pH1, g_pH1);
    cudaGetSymbolAddress((void**)&pL1, g_pL1);

    cudaFuncSetAttribute(gemm_mma, cudaFuncAttributeMaxDynamicSharedMemorySize,
                         GEMM_SMEM);

    static cudaStream_t s2 = nullptr;
    static cudaEvent_t evFork = nullptr, evG[3][NCHUNK], evM[2];
    if (!s2) {
        cudaStreamCreateWithFlags(&s2, cudaStreamNonBlocking);
        cudaEventCreateWithFlags(&evFork, cudaEventDisableTiming);
        for (int l = 0; l < 3; l++)
            for (int p = 0; p < NCHUNK; p++)
                cudaEventCreateWithFlags(&evG[l][p], cudaEventDisableTiming);
        for (int i = 0; i < 2; i++)
            cudaEventCreateWithFlags(&evM[i], cudaEventDisableTiming);
    }

    // Row chunking: YBLOCKS=391 y-blocks of 128 rows, split into NCHUNK chunks.
    int yPer = (YBLOCKS + NCHUNK - 1) / NCHUNK;   // 98
    int yBase[NCHUNK], yCnt[NCHUNK], nBase[NCHUNK], nEnd[NCHUNK];
    for (int p = 0; p < NCHUNK; p++) {
        yBase[p] = p * yPer;
        int ye = (p + 1) * yPer; if (ye > YBLOCKS) ye = YBLOCKS;
        yCnt[p] = ye - yBase[p];
        nBase[p] = yBase[p] * 128;
        nEnd[p] = ye * 128; if (nEnd[p] > N_NODES) nEnd[p] = N_NODES;
    }

    const float* inF[3] = {x, h1, h2};
    float* outF[3] = {h1, h2, out};
    __nv_bfloat16* inHp[3] = {pH0, pH1, pH0};
    __nv_bfloat16* inLp[3] = {pL0, pL1, pL0};
    __nv_bfloat16* outHp[3] = {pH1, pH0, pH1};
    __nv_bfloat16* outLp[3] = {pL1, pL0, pL1};
    const float* biasArr[3] = {b1, b2, b3};

    // Fork s2 off capture stream
    cudaEventRecord(evFork, 0);
    cudaStreamWaitEvent(s2, evFork, 0);

    // s2: CSR build — overlaps prep on s0
    zero_cnt_kernel<<<(N_NODES + 255) / 256, 256, 0, s2>>>(cnt);
    hist_kernel<<<(E_EDGES + 255) / 256, 256, 0, s2>>>(ei, cnt);
    scan_kernel<<<1, 1024, 0, s2>>>(cnt, rowptr, cursor);
    fill_kernel<<<(E_EDGES + 255) / 256, 256, 0, s2>>>(ei, cursor, srcs);

    // s0: weight + x plane prep
    prep_weights<<<(3 * KTOT * DIM + 255) / 256, 256>>>(
        W1_rel, W1_root, W2_rel, W2_root, W3_rel, W3_root, Bh, Bl);
    prep_x<<<(N_NODES * DIM / 4 + 255) / 256, 256>>>((const float4*)x, pH0, pL0);

    for (int L = 0; L < 3; L++) {
        if (L > 0) cudaStreamWaitEvent(s2, evM[L - 1], 0);  // gather needs full h_{L-1}
        // s2: gather chunks (serialize on s2; each records its event)
        for (int p = 0; p < NCHUNK; p++) {
            int nodes = nEnd[p] - nBase[p];
            gather_agg_kernel<<<(nodes + 3) / 4, 256, 0, s2>>>(
                (const float4*)inF[L], rowptr, srcs, aggH, aggL, nBase[p], nEnd[p]);
            cudaEventRecord(evG[L][p], s2);
        }
        // s0: GEMM chunks, each gated on its gather chunk
        for (int p = 0; p < NCHUNK; p++) {
            cudaStreamWaitEvent(0, evG[L][p], 0);
            dim3 grid(2, yCnt[p]);
            gemm_mma<<<grid, 256, GEMM_SMEM>>>(
                aggH, aggL, inHp[L], inLp[L],
                Bh + (size_t)L * KTOT * DIM, Bl + (size_t)L * KTOT * DIM,
                biasArr[L], outF[L], outHp[L], outLp[L],
                (L < 2) ? 1 : 0, yBase[p]);
        }
        if (L < 2) cudaEventRecord(evM[L], 0);
    }
}

// round 16
// speedup vs baseline: 1.2963x; 1.2963x over previous
#include <cuda_runtime.h>
#include <cuda_bf16.h>
#include <cstdint>

#define N_NODES 50000
#define E_EDGES 800000
#define DIM 256
#define KTOT 512

// ---------------------------------------------------------------------------
// Scratch (static device globals — no allocation allowed)
// ---------------------------------------------------------------------------
__device__ __nv_bfloat16 g_aggH[N_NODES * DIM];
__device__ __nv_bfloat16 g_aggL[N_NODES * DIM];
__device__ __nv_bfloat16 g_pH0[N_NODES * DIM];
__device__ __nv_bfloat16 g_pL0[N_NODES * DIM];
__device__ __nv_bfloat16 g_pH1[N_NODES * DIM];
__device__ __nv_bfloat16 g_pL1[N_NODES * DIM];
__device__ int   g_cnt[N_NODES];
__device__ int   g_rowptr[N_NODES + 1];
__device__ int   g_cursor[N_NODES];
__device__ int   g_srcs[E_EDGES];
__device__ __nv_bfloat16 g_Bh[3 * KTOT * DIM];
__device__ __nv_bfloat16 g_Bl[3 * KTOT * DIM];

// ---------------------------------------------------------------------------
// PTX helpers
// ---------------------------------------------------------------------------
__device__ __forceinline__ uint32_t smem_u32(const void* p) {
    uint32_t a;
    asm("{ .reg .u64 t; cvta.to.shared.u64 t, %1; cvt.u32.u64 %0, t; }"
        : "=r"(a) : "l"(p));
    return a;
}
__device__ __forceinline__ void ldm_x4(uint32_t* r, uint32_t addr) {
    asm volatile("ldmatrix.sync.aligned.m8n8.x4.shared.b16 {%0,%1,%2,%3}, [%4];"
                 : "=r"(r[0]), "=r"(r[1]), "=r"(r[2]), "=r"(r[3]) : "r"(addr));
}
__device__ __forceinline__ void ldm_x4_t(uint32_t* r, uint32_t addr) {
    asm volatile("ldmatrix.sync.aligned.m8n8.x4.trans.shared.b16 {%0,%1,%2,%3}, [%4];"
                 : "=r"(r[0]), "=r"(r[1]), "=r"(r[2]), "=r"(r[3]) : "r"(addr));
}
__device__ __forceinline__ void mma_bf16(float* c, const uint32_t* a, const uint32_t* b) {
    asm volatile("mma.sync.aligned.m16n8k16.row.col.f32.bf16.bf16.f32 "
                 "{%0,%1,%2,%3}, {%4,%5,%6,%7}, {%8,%9}, {%0,%1,%2,%3};"
                 : "+f"(c[0]), "+f"(c[1]), "+f"(c[2]), "+f"(c[3])
                 : "r"(a[0]), "r"(a[1]), "r"(a[2]), "r"(a[3]),
                   "r"(b[0]), "r"(b[1]));
}
__device__ __forceinline__ void cp16(uint32_t dst, const void* src, int szarg) {
    asm volatile("cp.async.cg.shared.global [%0], [%1], 16, %2;"
                 :: "r"(dst), "l"(src), "r"(szarg) : "memory");
}
__device__ __forceinline__ uint32_t pack_bf16(__nv_bfloat16 lo, __nv_bfloat16 hi) {
    return ((uint32_t)*(unsigned short*)&hi << 16) | *(unsigned short*)&lo;
}

// ---------------------------------------------------------------------------
// CSR build
// ---------------------------------------------------------------------------
__global__ void zero_cnt_kernel(int* __restrict__ cnt) {
    int i = blockIdx.x * blockDim.x + threadIdx.x;
    if (i < N_NODES) cnt[i] = 0;
}
__global__ void hist_kernel(const int* __restrict__ ei, int* __restrict__ cnt) {
    int e = blockIdx.x * blockDim.x + threadIdx.x;
    if (e < E_EDGES) {
        int d = ei[E_EDGES + e];
        if ((unsigned)d < N_NODES) atomicAdd(&cnt[d], 1);
    }
}
__global__ void scan_kernel(const int* __restrict__ cnt,
                            int* __restrict__ rowptr, int* __restrict__ cursor) {
    const int C = 49;
    int tid = threadIdx.x;
    int base = tid * C;
    int s = 0;
    for (int i = 0; i < C; i++) { int idx = base + i; if (idx < N_NODES) s += cnt[idx]; }
    int lane = tid & 31, warp = tid >> 5;
    int v = s;
#pragma unroll
    for (int o = 1; o < 32; o <<= 1) {
        int n = __shfl_up_sync(0xFFFFFFFFu, v, o);
        if (lane >= o) v += n;
    }
    __shared__ int wsum[32];
    if (lane == 31) wsum[warp] = v;
    __syncthreads();
    if (warp == 0) {
        int w = wsum[lane];
#pragma unroll
        for (int o = 1; o < 32; o <<= 1) {
            int n = __shfl_up_sync(0xFFFFFFFFu, w, o);
            if (lane >= o) w += n;
        }
        wsum[lane] = w;
    }
    __syncthreads();
    int excl = v - s + (warp > 0 ? wsum[warp - 1] : 0);
    int run = excl;
    for (int i = 0; i < C; i++) {
        int idx = base + i;
        if (idx < N_NODES) { rowptr[idx] = run; cursor[idx] = run; run += cnt[idx]; }
    }
    if (tid == blockDim.x - 1) rowptr[N_NODES] = run;
}
__global__ void fill_kernel(const int* __restrict__ ei,
                            int* __restrict__ cursor, int* __restrict__ srcs) {
    int e = blockIdx.x * blockDim.x + threadIdx.x;
    if (e < E_EDGES) {
        int d = ei[E_EDGES + e];
        int s = ei[e];
        if ((unsigned)d < N_NODES && (unsigned)s < N_NODES) {
            int p = atomicAdd(&cursor[d], 1);
            srcs[p] = s;
        }
    }
}

// ---------------------------------------------------------------------------
// Weight prep
// ---------------------------------------------------------------------------
__global__ void prep_weights(const float* __restrict__ W1r, const float* __restrict__ W1o,
                             const float* __restrict__ W2r, const float* __restrict__ W2o,
                             const float* __restrict__ W3r, const float* __restrict__ W3o,
                             __nv_bfloat16* __restrict__ Bh, __nv_bfloat16* __restrict__ Bl) {
    int i = blockIdx.x * blockDim.x + threadIdx.x;
    if (i >= 3 * KTOT * DIM) return;
    int layer = i / (KTOT * DIM);
    int rem = i % (KTOT * DIM);
    int k = rem >> 8;
    int n = rem & 255;
    const float* Wr = (layer == 0) ? W1r : (layer == 1) ? W2r : W3r;
    const float* Wo = (layer == 0) ? W1o : (layer == 1) ? W2o : W3o;
    float w = (k < 256) ? Wr[k * 256 + n] : Wo[(k - 256) * 256 + n];
    __nv_bfloat16 hi = __float2bfloat16(w);
    __nv_bfloat16 lo = __float2bfloat16(w - __bfloat162float(hi));
    Bh[i] = hi;
    Bl[i] = lo;
}

__global__ void prep_x(const float4* __restrict__ x4,
                       __nv_bfloat16* __restrict__ pH, __nv_bfloat16* __restrict__ pL) {
    int i = blockIdx.x * blockDim.x + threadIdx.x;
    if (i >= N_NODES * DIM / 4) return;
    float4 v = x4[i];
    __nv_bfloat16 h0 = __float2bfloat16(v.x), h1 = __float2bfloat16(v.y);
    __nv_bfloat16 h2 = __float2bfloat16(v.z), h3 = __float2bfloat16(v.w);
    __nv_bfloat16 l0 = __float2bfloat16(v.x - __bfloat162float(h0));
    __nv_bfloat16 l1 = __float2bfloat16(v.y - __bfloat162float(h1));
    __nv_bfloat16 l2 = __float2bfloat16(v.z - __bfloat162float(h2));
    __nv_bfloat16 l3 = __float2bfloat16(v.w - __bfloat162float(h3));
    *(uint2*)&pH[i * 4] = make_uint2(pack_bf16(h0, h1), pack_bf16(h2, h3));
    *(uint2*)&pL[i * 4] = make_uint2(pack_bf16(l0, l1), pack_bf16(l2, l3));
}

// ---------------------------------------------------------------------------
// Gathers: fp32-source (layer 0) and plane-source (layers 1,2).
// Both write bf16 hi/lo agg planes. fp32 accumulation.
// ---------------------------------------------------------------------------
__device__ __forceinline__ void store_split4(__nv_bfloat16* aggH, __nv_bfloat16* aggL,
                                             size_t o, const float* r) {
    __nv_bfloat16 h0 = __float2bfloat16(r[0]), h1 = __float2bfloat16(r[1]);
    __nv_bfloat16 h2 = __float2bfloat16(r[2]), h3 = __float2bfloat16(r[3]);
    __nv_bfloat16 l0 = __float2bfloat16(r[0] - __bfloat162float(h0));
    __nv_bfloat16 l1 = __float2bfloat16(r[1] - __bfloat162float(h1));
    __nv_bfloat16 l2 = __float2bfloat16(r[2] - __bfloat162float(h2));
    __nv_bfloat16 l3 = __float2bfloat16(r[3] - __bfloat162float(h3));
    *(uint2*)&aggH[o] = make_uint2(pack_bf16(h0, h1), pack_bf16(h2, h3));
    *(uint2*)&aggL[o] = make_uint2(pack_bf16(l0, l1), pack_bf16(l2, l3));
}

__global__ void gather_agg_f32(const float4* __restrict__ x4,
                               const int* __restrict__ rowptr,
                               const int* __restrict__ srcs,
                               __nv_bfloat16* __restrict__ aggH,
                               __nv_bfloat16* __restrict__ aggL) {
    int node = blockIdx.x * 4 + (threadIdx.x >> 6);
    int t = threadIdx.x & 63;
    if (node >= N_NODES) return;
    int beg = rowptr[node];
    int end = rowptr[node + 1];
    float4 a0 = make_float4(0.f, 0.f, 0.f, 0.f);
    float4 a1 = make_float4(0.f, 0.f, 0.f, 0.f);
    int e = beg;
    for (; e + 2 <= end; e += 2) {
        int s0 = srcs[e], s1 = srcs[e + 1];
        float4 v0 = x4[(size_t)s0 * 64 + t];
        float4 v1 = x4[(size_t)s1 * 64 + t];
        a0.x += v0.x; a0.y += v0.y; a0.z += v0.z; a0.w += v0.w;
        a1.x += v1.x; a1.y += v1.y; a1.z += v1.z; a1.w += v1.w;
    }
    if (e < end) {
        int s0 = srcs[e];
        float4 v0 = x4[(size_t)s0 * 64 + t];
        a0.x += v0.x; a0.y += v0.y; a0.z += v0.z; a0.w += v0.w;
    }
    float r[4] = {a0.x + a1.x, a0.y + a1.y, a0.z + a1.z, a0.w + a1.w};
    store_split4(aggH, aggL, (size_t)node * 256 + t * 4, r);
}

__device__ __forceinline__ void acc_planes(float* a, uint2 hp, uint2 lp) {
    float2 f;
    f = __bfloat1622float2(*(__nv_bfloat162*)&hp.x); a[0] += f.x; a[1] += f.y;
    f = __bfloat1622float2(*(__nv_bfloat162*)&hp.y); a[2] += f.x; a[3] += f.y;
    f = __bfloat1622float2(*(__nv_bfloat162*)&lp.x); a[0] += f.x; a[1] += f.y;
    f = __bfloat1622float2(*(__nv_bfloat162*)&lp.y); a[2] += f.x; a[3] += f.y;
}

__global__ void gather_agg_planes(const uint2* __restrict__ pH,
                                  const uint2* __restrict__ pL,
                                  const int* __restrict__ rowptr,
                                  const int* __restrict__ srcs,
                                  __nv_bfloat16* __restrict__ aggH,
                                  __nv_bfloat16* __restrict__ aggL) {
    int node = blockIdx.x * 4 + (threadIdx.x >> 6);
    int t = threadIdx.x & 63;
    if (node >= N_NODES) return;
    int beg = rowptr[node];
    int end = rowptr[node + 1];
    float a0[4] = {0.f, 0.f, 0.f, 0.f};
    float a1[4] = {0.f, 0.f, 0.f, 0.f};
    int e = beg;
    for (; e + 2 <= end; e += 2) {
        int s0 = srcs[e], s1 = srcs[e + 1];
        size_t i0 = (size_t)s0 * 64 + t, i1 = (size_t)s1 * 64 + t;
        uint2 h0 = pH[i0], l0 = pL[i0];
        uint2 h1 = pH[i1], l1 = pL[i1];
        acc_planes(a0, h0, l0);
        acc_planes(a1, h1, l1);
    }
    if (e < end) {
        int s0 = srcs[e];
        size_t i0 = (size_t)s0 * 64 + t;
        acc_planes(a0, pH[i0], pL[i0]);
    }
    float r[4] = {a0[0] + a1[0], a0[1] + a1[1], a0[2] + a1[2], a0[3] + a1[3]};
    store_split4(aggH, aggL, (size_t)node * 256 + t * 4, r);
}

// ---------------------------------------------------------------------------
// Tensor-core GEMM, BK=16, 2-stage cp.async, targeting 2 blocks/SM.
// 3-pass Markidis split. Block 128x128, 8 warps (32x64 warp tile).
// ---------------------------------------------------------------------------
#define A_ST 24     // elems; 48B rows -> ldmatrix conflict-free
#define B_ST 136    // elems; 272B rows
#define A_PL 6144   // 128*24*2 bytes
#define B_PL 4352   // 16*136*2 bytes
#define SM_AH(b) ((b) * A_PL)
#define SM_AL(b) (2 * A_PL + (b) * A_PL)
#define SM_BH(b) (4 * A_PL + (b) * B_PL)
#define SM_BL(b) (4 * A_PL + 2 * B_PL + (b) * B_PL)
#define GEMM_SMEM (4 * A_PL + 4 * B_PL)   // 41984

__device__ __forceinline__ void load_tile16(
    int it, uint32_t sAh, uint32_t sAl, uint32_t sBh, uint32_t sBl,
    int tid, int rowBase, int colBase,
    const __nv_bfloat16* aggH, const __nv_bfloat16* aggL,
    const __nv_bfloat16* inH, const __nv_bfloat16* inL,
    const __nv_bfloat16* BhG, const __nv_bfloat16* BlG) {
    int kglob = it * 16;
    const __nv_bfloat16* AH = (it < 16) ? aggH : inH;
    const __nv_bfloat16* AL = (it < 16) ? aggL : inL;
    int kc = kglob & 255;
    {   // A: 128 rows x 16 cols, 2 chunks/row, 256 chunks/plane, 1 per thread
        int r = tid >> 1, c = tid & 1;
        int row = rowBase + r;
        int ok = (row < N_NODES);
        size_t off = (size_t)(ok ? row : 0) * 256 + kc + c * 8;
        int sz = ok ? 16 : 0;
        cp16(sAh + r * 48 + c * 16, AH + off, sz);
        cp16(sAl + r * 48 + c * 16, AL + off, sz);
    }
    {   // B: 16 rows x 128 cols, 16 chunks/row, 256 chunks/plane, 1 per thread
        int r = tid >> 4, c = tid & 15;
        size_t off = (size_t)(kglob + r) * 256 + colBase + c * 8;
        cp16(sBh + r * 272 + c * 16, BhG + off, 16);
        cp16(sBl + r * 272 + c * 16, BlG + off, 16);
    }
    asm volatile("cp.async.commit_group;" ::: "memory");
}

__global__ void __launch_bounds__(256, 2)
gemm_mma(const __nv_bfloat16* __restrict__ aggH, const __nv_bfloat16* __restrict__ aggL,
         const __nv_bfloat16* __restrict__ inH, const __nv_bfloat16* __restrict__ inL,
         const __nv_bfloat16* __restrict__ BhG, const __nv_bfloat16* __restrict__ BlG,
         const float* __restrict__ bias, float* __restrict__ outF,
         __nv_bfloat16* __restrict__ outH, __nv_bfloat16* __restrict__ outL) {
    extern __shared__ char smem[];
    uint32_t sb = smem_u32(smem);
    int tid = threadIdx.x;
    int wid = tid >> 5;
    int lane = tid & 31;
    int rowBase = blockIdx.y * 128;
    int colBase = blockIdx.x * 128;
    int wm = wid >> 1;
    int wn = wid & 1;

    float acc[2][8][4];
#pragma unroll
    for (int i = 0; i < 2; i++)
#pragma unroll
        for (int j = 0; j < 8; j++)
#pragma unroll
            for (int q = 0; q < 4; q++) acc[i][j][q] = 0.f;

    load_tile16(0, sb + SM_AH(0), sb + SM_AL(0), sb + SM_BH(0), sb + SM_BL(0),
                tid, rowBase, colBase, aggH, aggL, inH, inL, BhG, BlG);

    for (int it = 0; it < 32; it++) {
        int buf = it & 1;
        if (it < 31) {
            int nb = buf ^ 1;
            load_tile16(it + 1, sb + SM_AH(nb), sb + SM_AL(nb), sb + SM_BH(nb), sb + SM_BL(nb),
                        tid, rowBase, colBase, aggH, aggL, inH, inL, BhG, BlG);
            asm volatile("cp.async.wait_group 1;" ::: "memory");
        } else {
            asm volatile("cp.async.wait_group 0;" ::: "memory");
        }
        __syncthreads();

        uint32_t Ah = sb + SM_AH(buf), Al = sb + SM_AL(buf);
        uint32_t Bh = sb + SM_BH(buf), Bl = sb + SM_BL(buf);

        uint32_t ah[2][4], al[2][4];
        int arow = wm * 32 + (lane & 15);
        int akk = (lane >> 4) * 8;
#pragma unroll
        for (int mb = 0; mb < 2; mb++) {
            ldm_x4(ah[mb], Ah + ((arow + mb * 16) * A_ST + akk) * 2);
            ldm_x4(al[mb], Al + ((arow + mb * 16) * A_ST + akk) * 2);
        }
        int brow = lane & 15;
#pragma unroll
        for (int np = 0; np < 4; np++) {
            int ncol = wn * 64 + np * 16 + (lane >> 4) * 8;
            uint32_t rh[4], rl[4];
            ldm_x4_t(rh, Bh + (brow * B_ST + ncol) * 2);
            ldm_x4_t(rl, Bl + (brow * B_ST + ncol) * 2);
#pragma unroll
            for (int half = 0; half < 2; half++) {
                uint32_t bh2[2] = {rh[half * 2], rh[half * 2 + 1]};
                uint32_t bl2[2] = {rl[half * 2], rl[half * 2 + 1]};
                int nb = np * 2 + half;
#pragma unroll
                for (int mb = 0; mb < 2; mb++) {
                    mma_bf16(acc[mb][nb], ah[mb], bh2);
                    mma_bf16(acc[mb][nb], ah[mb], bl2);
                    mma_bf16(acc[mb][nb], al[mb], bh2);
                }
            }
        }
        __syncthreads();
    }

    // --- epilogue: bias + ELU; write fp32 (last layer) or bf16 planes ---
#pragma unroll
    for (int mb = 0; mb < 2; mb++) {
        int row0 = rowBase + wm * 32 + mb * 16 + (lane >> 2);
#pragma unroll
        for (int nb = 0; nb < 8; nb++) {
            int col = colBase + wn * 64 + nb * 8 + (lane & 3) * 2;
            float b0 = bias[col], b1 = bias[col + 1];
#pragma unroll
            for (int half = 0; half < 2; half++) {
                int row = row0 + half * 8;
                if (row >= N_NODES) continue;
                float v0 = acc[mb][nb][half * 2 + 0] + b0;
                float v1 = acc[mb][nb][half * 2 + 1] + b1;
                v0 = (v0 > 0.f) ? v0 : expm1f(v0);
                v1 = (v1 > 0.f) ? v1 : expm1f(v1);
                size_t o = (size_t)row * 256 + col;
                if (outF) {
                    *(float2*)(outF + o) = make_float2(v0, v1);
                } else {
                    __nv_bfloat16 h0 = __float2bfloat16(v0);
                    __nv_bfloat16 h1 = __float2bfloat16(v1);
                    __nv_bfloat16 l0 = __float2bfloat16(v0 - __bfloat162float(h0));
                    __nv_bfloat16 l1 = __float2bfloat16(v1 - __bfloat162float(h1));
                    *(uint32_t*)&outH[o] = pack_bf16(h0, h1);
                    *(uint32_t*)&outL[o] = pack_bf16(l0, l1);
                }
            }
        }
    }
}

// ---------------------------------------------------------------------------
// Launch (single stream, R13 structure)
// ---------------------------------------------------------------------------
extern "C" void kernel_launch(void* const* d_in, const int* in_sizes, int n_in,
                              void* d_out, int out_size) {
    const float* x       = (const float*)d_in[0];
    const int*   ei      = (const int*)d_in[1];
    const float* W1_rel  = (const float*)d_in[2];
    const float* b1      = (const float*)d_in[3];
    const float* W1_root = (const float*)d_in[4];
    const float* W2_rel  = (const float*)d_in[5];
    const float* b2      = (const float*)d_in[6];
    const float* W2_root = (const float*)d_in[7];
    const float* W3_rel  = (const float*)d_in[8];
    const float* b3      = (const float*)d_in[9];
    const float* W3_root = (const float*)d_in[10];
    float* out = (float*)d_out;

    int *cnt, *rowptr, *cursor, *srcs;
    __nv_bfloat16 *Bh, *Bl, *aggH, *aggL, *pH0, *pL0, *pH1, *pL1;
    cudaGetSymbolAddress((void**)&cnt, g_cnt);
    cudaGetSymbolAddress((void**)&rowptr, g_rowptr);
    cudaGetSymbolAddress((void**)&cursor, g_cursor);
    cudaGetSymbolAddress((void**)&srcs, g_srcs);
    cudaGetSymbolAddress((void**)&Bh, g_Bh);
    cudaGetSymbolAddress((void**)&Bl, g_Bl);
    cudaGetSymbolAddress((void**)&aggH, g_aggH);
    cudaGetSymbolAddress((void**)&aggL, g_aggL);
    cudaGetSymbolAddress((void**)&pH0, g_pH0);
    cudaGetSymbolAddress((void**)&pL0, g_pL0);
    cudaGetSymbolAddress((void**)&pH1, g_pH1);
    cudaGetSymbolAddress((void**)&pL1, g_pL1);

    cudaFuncSetAttribute(gemm_mma, cudaFuncAttributeMaxDynamicSharedMemorySize,
                         GEMM_SMEM);

    // CSR build
    zero_cnt_kernel<<<(N_NODES + 255) / 256, 256>>>(cnt);
    hist_kernel<<<(E_EDGES + 255) / 256, 256>>>(ei, cnt);
    scan_kernel<<<1, 1024>>>(cnt, rowptr, cursor);
    fill_kernel<<<(E_EDGES + 255) / 256, 256>>>(ei, cursor, srcs);
    // Weight + x planes
    prep_weights<<<(3 * KTOT * DIM + 255) / 256, 256>>>(
        W1_rel, W1_root, W2_rel, W2_root, W3_rel, W3_root, Bh, Bl);
    prep_x<<<(N_NODES * DIM / 4 + 255) / 256, 256>>>((const float4*)x, pH0, pL0);

    // Ping-pong feature planes: L0 in=pH0 (x), out planes=pH1 (h1);
    // L1 in=pH1, out planes=pH0 (h2, x planes dead); L2 in=pH0, out=fp32 d_out.
    __nv_bfloat16* inHp[3]  = {pH0, pH1, pH0};
    __nv_bfloat16* inLp[3]  = {pL0, pL1, pL0};
    __nv_bfloat16* outHp[3] = {pH1, pH0, nullptr};
    __nv_bfloat16* outLp[3] = {pL1, pL0, nullptr};
    const float* biasArr[3] = {b1, b2, b3};

    dim3 ggrid(2, (N_NODES + 127) / 128);
    for (int L = 0; L < 3; L++) {
        if (L == 0) {
            gather_agg_f32<<<(N_NODES + 3) / 4, 256>>>(
                (const float4*)x, rowptr, srcs, aggH, aggL);
        } else {
            gather_agg_planes<<<(N_NODES + 3) / 4, 256>>>(
                (const uint2*)inHp[L], (const uint2*)inLp[L], rowptr, srcs, aggH, aggL);
        }
        gemm_mma<<<ggrid, 256, GEMM_SMEM>>>(
            aggH, aggL, inHp[L], inLp[L],
            Bh + (size_t)L * KTOT * DIM, Bl + (size_t)L * KTOT * DIM,
            biasArr[L], (L == 2) ? out : nullptr, outHp[L], outLp[L]);
    }
}